// round 17
// baseline (speedup 1.0000x reference)
#include <cuda_runtime.h>
#include <cuda_bf16.h>

#define NKER 25
#define HP   8        // padded inner dim (6 feats + basis-sum + pad)
#define HROW 200      // NKER * HP floats per node
#define HW   150      // logical 25*6
#define JD   156      // 150 + 6 (H rows + x rows)
#define CD   78       // 75 Z cols + 3 root cols
#define HMP  42       // zgemm half-M smem pitch (40 cols + 2 pad)
#define NMAX 50000
#define EMAX 1600000

// scratch (no cudaMalloc allowed)
__device__ float  g_H[NMAX * HROW];     // 40 MB
__device__ float  g_inv[NMAX];
__device__ float4 g_X8[NMAX * 2];       // x packed 32B-aligned: {x0..x5,0,0}
__device__ float4 g_Z4[NMAX * NKER];    // 20 MB, (z0,z1,z2,pad) per (n,kk)
__device__ float4 g_A4[NMAX];           // edge-2 accumulator
__device__ float  g_M[JD * CD];         // fused weight matrix

// ---- packed f32x2 helpers ---------------------------------------------------
__device__ __forceinline__ unsigned long long pack2(float lo, float hi) {
    unsigned long long r;
    asm("mov.b64 %0, {%1, %2};" : "=l"(r) : "f"(lo), "f"(hi));
    return r;
}
__device__ __forceinline__ void unpack2(unsigned long long v, float& lo, float& hi) {
    asm("mov.b64 {%0, %1}, %2;" : "=f"(lo), "=f"(hi) : "l"(v));
}
#define FFMA2(acc, a2, b2) \
    asm("fma.rn.f32x2 %0, %1, %2, %0;" : "+l"(acc) : "l"(a2), "l"(b2))
__device__ __forceinline__ unsigned long long mul2(unsigned long long a,
                                                   unsigned long long b) {
    unsigned long long d;
    asm("mul.rn.f32x2 %0, %1, %2;" : "=l"(d) : "l"(a), "l"(b));
    return d;
}

// ---------------------------------------------------------------------------
__global__ void k_zero(const float* __restrict__ x, int N) {
    int i = blockIdx.x * blockDim.x + threadIdx.x;
    int stride = gridDim.x * blockDim.x;
    float4 z4 = make_float4(0.f, 0.f, 0.f, 0.f);
    float4* H4 = reinterpret_cast<float4*>(g_H);
    int nH4 = N * (HROW / 4);
    for (int t = i; t < nH4; t += stride) H4[t] = z4;
    for (int t = i; t < N; t += stride) {
        g_A4[t] = z4;
        const float2* x2 = reinterpret_cast<const float2*>(x) + t * 3;
        float2 xa = x2[0], xb = x2[1], xc = x2[2];
        g_X8[2 * t]     = make_float4(xa.x, xa.y, xb.x, xb.y);
        g_X8[2 * t + 1] = make_float4(xc.x, xc.y, 0.f, 0.f);
    }
}

// degree-1 open B-spline, K=5: 4 corners
__device__ __forceinline__ void spline4(float p0, float p1, float* b, int* id) {
    float v0 = p0 * 4.0f, v1 = p1 * 4.0f;
    float fl0 = floorf(v0), fl1 = floorf(v1);
    int i0 = (int)fl0, i1 = (int)fl1;
    i0 = min(max(i0, 0), 3);
    i1 = min(max(i1, 0), 3);
    float f0 = v0 - fl0, f1 = v1 - fl1;
    float g0 = 1.0f - f0, g1 = 1.0f - f1;
    b[0] = g0 * g1; b[1] = f0 * g1; b[2] = g0 * f1; b[3] = f0 * f1;
    int base = i0 + 5 * i1;
    id[0] = base; id[1] = base + 1; id[2] = base + 5; id[3] = base + 6;
}

// ---------------------------------------------------------------------------
// Fused edge1 + buildM: blocks [0, JD) build M; blocks [JD, ...) do edge pass 1.
__global__ void __launch_bounds__(256)
k_edge1_buildM(const int* __restrict__ ei, const float* __restrict__ ps, int E,
               const float* __restrict__ w, const float* __restrict__ rw,
               const float* __restrict__ w1, const float* __restrict__ rw1) {
    __shared__ float sA[1024];
    __shared__ float red[CD][2];
    int tid = threadIdx.x;

    if (blockIdx.x < JD) {
        // ---- buildM role: M[j, :] = Arow(1024) @ Wc(1024 x 78) ----
        int j = blockIdx.x;
        const float* Arow = (j < HW) ? (w + (j / 6) * 6144 + (j % 6) * 1024)
                                     : (rw + (j - HW) * 1024);
        for (int i = tid; i < 1024; i += 256) sA[i] = Arow[i];
        __syncthreads();
        int c = tid >> 1, sl = tid & 1;
        if (c < CD) {
            const float* Bp = (c < 75) ? (w1 + (c / 3) * 3072 + (c % 3))
                                       : (rw1 + (c - 75));
            float acc = 0.f;
            int i0 = sl * 512;
#pragma unroll 8
            for (int i = i0; i < i0 + 512; i++)
                acc = fmaf(sA[i], __ldg(Bp + i * 3), acc);
            red[c][sl] = acc;
        }
        __syncthreads();
        if (tid < CD)
            g_M[j * CD + tid] = red[tid][0] + red[tid][1];
        return;
    }

    // ---- edge1 role ----
    int e = (blockIdx.x - JD) * 256 + tid;
    if (e >= E) return;
    int dst = ei[e];
    int src = ei[E + e];
    float2 p = reinterpret_cast<const float2*>(ps)[e];
    float b[4]; int id[4];
    spline4(p.x, p.y, b, id);
    float4 xa = __ldg(g_X8 + 2 * src);
    float4 xb = __ldg(g_X8 + 2 * src + 1);
    float4* Hd = reinterpret_cast<float4*>(g_H + (size_t)dst * HROW);
#pragma unroll
    for (int s = 0; s < 4; s++) {
        float bs = b[s];
        float4* hp = Hd + id[s] * 2;
        atomicAdd(hp,     make_float4(bs * xa.x, bs * xa.y, bs * xa.z, bs * xa.w));
        atomicAdd(hp + 1, make_float4(bs * xb.x, bs * xb.y, bs, 0.f));
    }
}

// ---------------------------------------------------------------------------
// Z GEMM, f32x2, ONE node-half per thread (low regs -> high residency).
// blockIdx.y = half (39 cols). Per j-row: 10 LDS.128 + 1 pack + 20 FFMA2.
__global__ void __launch_bounds__(128, 4)
k_zgemm(float* __restrict__ dout, int N) {
    __shared__ float sB[JD * HMP];   // 156*42*4 = 26208 B (static, < 48KB)
    int tid = threadIdx.x;
    int half = blockIdx.y;
    int n = blockIdx.x * 128 + tid;

    for (int idx = tid; idx < JD * 40; idx += 128) {
        int j = idx / 40, lc = idx - j * 40;
        sB[j * HMP + lc] = (lc < 39) ? g_M[j * CD + half * 39 + lc] : 0.f;
    }
    __syncthreads();
    if (n >= N) return;

    unsigned long long acc[20];
#pragma unroll
    for (int p = 0; p < 20; p++) acc[p] = 0ull;

    const float4* H = reinterpret_cast<const float4*>(g_H + (size_t)n * HROW);
    float d = 0.f;

    for (int k = 0; k < NKER; k++) {
        float4 h0 = __ldg(H + 2 * k);
        float4 h1 = __ldg(H + 2 * k + 1);
        d += h1.z;
        float av[6] = {h0.x, h0.y, h0.z, h0.w, h1.x, h1.y};
#pragma unroll
        for (int i = 0; i < 6; i++) {
            const double2* row = reinterpret_cast<const double2*>(
                sB + (k * 6 + i) * HMP);
            unsigned long long a2 = pack2(av[i], av[i]);
#pragma unroll
            for (int p = 0; p < 10; p++) {
                double2 bb = row[p];
                unsigned long long b0 = __double_as_longlong(bb.x);
                unsigned long long b1 = __double_as_longlong(bb.y);
                FFMA2(acc[2 * p],     a2, b0);
                FFMA2(acc[2 * p + 1], a2, b1);
            }
        }
    }

    float inv = 1.0f / fmaxf(d, 1.0f);
    if (half == 0) g_inv[n] = inv;
    unsigned long long i2 = pack2(inv, inv);
#pragma unroll
    for (int p = 0; p < 20; p++) acc[p] = mul2(acc[p], i2);

    // x part (rows 150..155 of M), unscaled
    float4 xa = __ldg(g_X8 + 2 * n);
    float4 xb = __ldg(g_X8 + 2 * n + 1);
    float xv[6] = {xa.x, xa.y, xa.z, xa.w, xb.x, xb.y};
#pragma unroll
    for (int i = 0; i < 6; i++) {
        const double2* row = reinterpret_cast<const double2*>(
            sB + (HW + i) * HMP);
        unsigned long long a2 = pack2(xv[i], xv[i]);
#pragma unroll
        for (int p = 0; p < 10; p++) {
            double2 bb = row[p];
            unsigned long long b0 = __double_as_longlong(bb.x);
            unsigned long long b1 = __double_as_longlong(bb.y);
            FFMA2(acc[2 * p],     a2, b0);
            FFMA2(acc[2 * p + 1], a2, b1);
        }
    }

    float f[40];
#pragma unroll
    for (int p = 0; p < 20; p++) unpack2(acc[p], f[2 * p], f[2 * p + 1]);

    float4* Zn = g_Z4 + (size_t)n * NKER;
    if (half == 0) {
#pragma unroll
        for (int g = 0; g < 13; g++)
            Zn[g] = make_float4(f[3 * g], f[3 * g + 1], f[3 * g + 2], 0.f);
    } else {
#pragma unroll
        for (int g = 0; g < 12; g++)
            Zn[13 + g] = make_float4(f[3 * g], f[3 * g + 1], f[3 * g + 2], 0.f);
        dout[n * 3 + 0] = f[36];
        dout[n * 3 + 1] = f[37];
        dout[n * 3 + 2] = f[38];
    }
}

// ---------------------------------------------------------------------------
// Edge pass 2: A4[dst] += sum_s basis1_s * Z[src, idx_s, :]  (one float4 atomic)
__global__ void k_edge2(const int* __restrict__ ei, const float* __restrict__ ps,
                        int E) {
    int e = blockIdx.x * blockDim.x + threadIdx.x;
    if (e >= E) return;
    int dst = ei[e];
    int src = ei[E + e];
    float2 p = reinterpret_cast<const float2*>(ps)[e];
    float b[4]; int id[4];
    spline4(p.x, p.y, b, id);
    const float4* Z = g_Z4 + (size_t)src * NKER;
    float a0 = 0.f, a1 = 0.f, a2 = 0.f;
#pragma unroll
    for (int s = 0; s < 4; s++) {
        float4 z = __ldg(Z + id[s]);
        a0 = fmaf(b[s], z.x, a0);
        a1 = fmaf(b[s], z.y, a1);
        a2 = fmaf(b[s], z.z, a2);
    }
    atomicAdd(g_A4 + dst, make_float4(a0, a1, a2, 0.f));
}

// ---------------------------------------------------------------------------
// Final: out[n] = root_term (already in dout) + inv[n] * A4[n]
__global__ void k_final(float* __restrict__ dout, int N) {
    int n = blockIdx.x * blockDim.x + threadIdx.x;
    if (n >= N) return;
    float4 a = g_A4[n];
    float inv = g_inv[n];
    dout[n * 3 + 0] += a.x * inv;
    dout[n * 3 + 1] += a.y * inv;
    dout[n * 3 + 2] += a.z * inv;
}

// ---------------------------------------------------------------------------
extern "C" void kernel_launch(void* const* d_in, const int* in_sizes, int n_in,
                              void* d_out, int out_size) {
    const float* x   = (const float*)d_in[0];
    const int*   ei  = (const int*)d_in[1];
    const float* ps  = (const float*)d_in[2];
    const float* ps1 = (const float*)d_in[3];
    const float* w   = (const float*)d_in[4];
    const float* rw  = (const float*)d_in[5];
    const float* w1  = (const float*)d_in[6];
    const float* rw1 = (const float*)d_in[7];
    float* dout = (float*)d_out;

    int N = in_sizes[0] / 6;
    int E = in_sizes[2] / 2;
    if (N > NMAX) N = NMAX;
    if (E > EMAX) E = EMAX;

    k_zero<<<2048, 256>>>(x, N);
    int edgeBlocks = (E + 255) / 256;
    k_edge1_buildM<<<JD + edgeBlocks, 256>>>(ei, ps, E, w, rw, w1, rw1);

    dim3 gz((N + 127) / 128, 2);
    k_zgemm<<<gz, 128>>>(dout, N);

    k_edge2<<<(E + 255) / 256, 256>>>(ei, ps1, E);
    k_final<<<(N + 255) / 256, 256>>>(dout, N);
}